// round 17
// baseline (speedup 1.0000x reference)
#include <cuda_runtime.h>
#include <math.h>
#include <cstdint>

namespace {
constexpr int Hn  = 256;   // heads
constexpr int NH  = 64;    // complex modes per head
constexpr int Lk  = 2048;  // kernel length
constexpr int FN  = 1024;  // half-size complex IFFT length
constexpr float TWO_PI = 6.28318530717958647692f;
constexpr float PI_F   = 3.14159265358979323846f;
}

__device__ __forceinline__ float frcp(float x) {
    float r; asm("rcp.approx.f32 %0, %1;" : "=f"(r) : "f"(x)); return r;
}
// tf32 hi part: keep bits [31:13]. Exact, ALU-pipe op.
__device__ __forceinline__ uint32_t tf32_hi_bits(float x) {
    return __float_as_uint(x) & 0xFFFFE000u;
}
// D[16x8] += A[16x8,row] * B[8x8,col]   (tf32 in regs as fp32 bits, f32 acc)
__device__ __forceinline__ void mma_tf32(float* d, const uint32_t* a,
                                         uint32_t b0, uint32_t b1) {
    asm volatile(
        "mma.sync.aligned.m16n8k8.row.col.f32.tf32.tf32.f32 "
        "{%0,%1,%2,%3}, {%4,%5,%6,%7}, {%8,%9}, {%0,%1,%2,%3};"
        : "+f"(d[0]), "+f"(d[1]), "+f"(d[2]), "+f"(d[3])
        : "r"(a[0]), "r"(a[1]), "r"(a[2]), "r"(a[3]), "r"(b0), "r"(b1));
}

// ---------------------------------------------------------------------------
// Fused kernel, 512 threads, min 3 blocks/SM: 1 block = 1 head.
// Phase 1: 1025-bin spectrum via tf32-split warp MMA; W hi/lo pre-split in
//          smem (loaded per k-tile, conflict-free) to free 32 regs/thread.
// Phase 2: real IFFT via half-size (1024-pt) complex IFFT, 5 radix-4 stages.
// ---------------------------------------------------------------------------
__global__ void __launch_bounds__(512, 3) k_fused(
    const float* __restrict__ w_ri,
    const float* __restrict__ P_ri,
    const float* __restrict__ B_ri,
    const float* __restrict__ C_ri,
    const float* __restrict__ log_dt,
    float* __restrict__ out)
{
    __shared__ float2   zbuf[2 * FN];    // 16 KB (IFFT ping+pong; sEx alias)
    __shared__ float2   kfs[1026];       // 8.2 KB spectrum (1025 used)
    __shared__ float4   sC[NH];          // {m2, cs, csq, 0}  1 KB
    __shared__ uint32_t sWh[NH * 8];     // W hi (tf32 bits)  2 KB
    __shared__ uint32_t sWl[NH * 8];     // W lo              2 KB
    __shared__ float    sY2[1024];       // y^2 per bin       4 KB
    // total static smem ~33.4 KB

    const int h    = blockIdx.x;
    const int tid  = threadIdx.x;
    const int wid  = tid >> 5;           // 0..15
    const int lane = tid & 31;
    const int g    = lane >> 2;          // fragment group (row / B col)
    const int tig  = lane & 3;

    // sEx aliased into zbuf (unused during phase 1): 16 warps x 16 x 16 floats
    float (*sEx)[16][16] = reinterpret_cast<float (*)[16][16]>(zbuf);

    // ---- per-head constants + W (pre-split tf32 hi/lo) ----
    if (tid < NH) {
        const int m = tid;
        const float dt = expf(log_dt[h]);
        const int base = (h * NH + m) * 2;
        const float wx = w_ri[base] * dt, wy = w_ri[base + 1] * dt;
        const float pr = P_ri[base], pi = P_ri[base + 1];
        const float br = B_ri[base], bi = B_ri[base + 1];
        const float cr = C_ri[base], ci = C_ri[base + 1];
        const float v00r = dt * (br * cr - bi * ci), v00i = dt * (br * ci + bi * cr);
        const float v01r = dt * (br * pr + bi * pi), v01i = dt * (bi * pr - br * pi);
        const float v10r = dt * (pr * cr - pi * ci), v10i = dt * (pr * ci + pi * cr);
        const float v11r = dt * (pr * pr + pi * pi);
        const float cs = 2.0f * wx;
        sC[m] = make_float4(wx * wx + wy * wy, cs, cs * cs, 0.0f);
        float wv[8];
        wv[0] = 2.0f * v00r; wv[1] = 2.0f * (v00r * wx + v00i * wy);
        wv[2] = 2.0f * v01r; wv[3] = 2.0f * (v01r * wx + v01i * wy);
        wv[4] = 2.0f * v10r; wv[5] = 2.0f * (v10r * wx + v10i * wy);
        wv[6] = 2.0f * v11r; wv[7] = 2.0f * v11r * wx;
#pragma unroll
        for (int r = 0; r < 8; r++) {
            const uint32_t hi = tf32_hi_bits(wv[r]);
            sWh[m * 8 + r] = hi;
            sWl[m * 8 + r] = __float_as_uint(wv[r] - __uint_as_float(hi));
        }
    }
    // per-bin y^2 for all 1024 bins (y >= 0 on [0, pi/2): recover y = sqrt)
    for (int idx = tid; idx < 1024; idx += 512) {
        const float y = 2.0f * tanf(PI_F / (float)Lk * (float)idx);
        sY2[idx] = y * y;
    }
    // Nyquist bin: analytic limit = sum Re(dt*B*C), real
    if (tid == 0) {
        const float dt = expf(log_dt[h]);
        float acc = 0.0f;
        for (int m = 0; m < NH; m++) {
            const int base = (h * NH + m) * 2;
            acc += B_ri[base] * C_ri[base] - B_ri[base + 1] * C_ri[base + 1];
        }
        kfs[1024] = make_float2(dt * acc, 0.0f);
    }
    __syncthreads();

    // ---- phase 1: 4 tiles of 16 bins per warp (16 warps cover 64 tiles) ----
#pragma unroll 1
    for (int it = 0; it < 4; it++) {
        const int base_bin = (wid * 4 + it) * 16;
        const float yA2 = sY2[base_bin + g];
        const float yB2 = sY2[base_bin + g + 8];

        float D1[4] = {0, 0, 0, 0}, D2[4] = {0, 0, 0, 0};

#pragma unroll
        for (int kt = 0; kt < 8; kt++) {
            const int n0 = 8 * kt + tig;
            const int n1 = n0 + 4;
            const float4 c0 = sC[n0];
            const float4 c1 = sC[n1];

            const float u00 = c0.x - yA2;
            const float q00 = frcp(fmaf(u00, u00, c0.z * yA2));
            const float u01 = c0.x - yB2;
            const float q01 = frcp(fmaf(u01, u01, c0.z * yB2));
            const float u10 = c1.x - yA2;
            const float q10 = frcp(fmaf(u10, u10, c1.z * yA2));
            const float u11 = c1.x - yB2;
            const float q11 = frcp(fmaf(u11, u11, c1.z * yB2));

            // B fragments from smem (conflict-free: banks (tig*8+g)%32 distinct)
            const uint32_t bh0 = sWh[n0 * 8 + g], bh1 = sWh[n1 * 8 + g];
            const uint32_t bl0 = sWl[n0 * 8 + g], bl1 = sWl[n1 * 8 + g];

            float p[4];
            p[0] = u00 * q00; p[1] = u01 * q01; p[2] = u10 * q10; p[3] = u11 * q11;
            uint32_t ah[4], al[4];
#pragma unroll
            for (int e = 0; e < 4; e++) {
                ah[e] = tf32_hi_bits(p[e]);
                al[e] = __float_as_uint(p[e] - __uint_as_float(ah[e]));
            }
            mma_tf32(D1, ah, bh0, bh1);
            mma_tf32(D1, ah, bl0, bl1);
            mma_tf32(D1, al, bh0, bh1);

            p[0] = c0.y * q00; p[1] = c0.y * q01; p[2] = c1.y * q10; p[3] = c1.y * q11;
#pragma unroll
            for (int e = 0; e < 4; e++) {
                ah[e] = tf32_hi_bits(p[e]);
                al[e] = __float_as_uint(p[e] - __uint_as_float(ah[e]));
            }
            mma_tf32(D2, ah, bh0, bh1);
            mma_tf32(D2, ah, bl0, bl1);
            mma_tf32(D2, al, bh0, bh1);
        }

        // transpose D fragments so one lane owns one bin
        sEx[wid][g][2 * tig]         = D1[0];
        sEx[wid][g][2 * tig + 1]     = D1[1];
        sEx[wid][g + 8][2 * tig]     = D1[2];
        sEx[wid][g + 8][2 * tig + 1] = D1[3];
        sEx[wid][g][8 + 2 * tig]         = D2[0];
        sEx[wid][g][8 + 2 * tig + 1]     = D2[1];
        sEx[wid][g + 8][8 + 2 * tig]     = D2[2];
        sEx[wid][g + 8][8 + 2 * tig + 1] = D2[3];
        __syncwarp();

        if (lane < 16) {
            const int j = base_bin + lane;
            const float y2 = sY2[j];
            const float y  = sqrtf(y2);
            const float* v = sEx[wid][lane];
            float rr[4], ri[4];
#pragma unroll
            for (int k = 0; k < 4; k++) {
                rr[k] = -fmaf(y2, v[8 + 2 * k], v[2 * k + 1]);
                ri[k] = y * (v[2 * k] - v[8 + 2 * k + 1]);
            }
            const float qr = 1.0f + rr[3], qi = ri[3];
            const float qn = frcp(fmaf(qr, qr, qi * qi));
            const float tr = rr[1] * rr[2] - ri[1] * ri[2];
            const float ti = rr[1] * ri[2] + ri[1] * rr[2];
            const float kr = rr[0] - (tr * qr + ti * qi) * qn;
            const float ki = ri[0] - (ti * qr - tr * qi) * qn;
            const float hh = 0.5f * y;
            kfs[j] = make_float2(fmaf(-ki, hh, kr), fmaf(kr, hh, ki));
        }
        __syncwarp();   // sEx reads done before next tile overwrites
    }
    __syncthreads();    // spectrum complete (retires sEx alias of zbuf)

    // ---- phase 2: half-size real IFFT -----------------------------------
    // pre-stage: Z[j] = A + i*B, A = a + conj(bc), B = (a - conj(bc)) * tw
    float2* zA = zbuf;
    float2* zB = zbuf + FN;
#pragma unroll
    for (int j = tid; j < FN; j += 512) {
        const float2 a  = kfs[j];
        const float2 bc = kfs[1024 - j];      // b = conj(bc); j=0 -> kfs[1024]
        const float Ax = a.x + bc.x, Ay = a.y - bc.y;
        const float Cx = a.x - bc.x, Cy = a.y + bc.y;
        float s, c;
        __sincosf(TWO_PI / (float)Lk * (float)j, &s, &c);
        const float Bx = Cx * c - Cy * s;
        const float By = Cx * s + Cy * c;
        zA[j] = make_float2(Ax - By, Ay + Bx);   // A + i*B
    }
    __syncthreads();

    // 5 radix-4 Stockham passes on 1024 points (s = 0,2,4,6,8)
    float2* cur = zA;
    float2* nxt = zB;
#pragma unroll
    for (int s = 0; s <= 8; s += 2) {
        const float step = TWO_PI * (float)(1 << s) / (float)FN;
        if (tid < FN / 4) {
            const int g2 = tid;
            const int p  = g2 >> s;
            const int lo = g2 & ((1 << s) - 1);
            const int u1 = (p << s) | lo;
            const int u2 = u1 + FN / 4;
            const float2 x0 = cur[u1], x2 = cur[u1 + FN / 2];
            const float2 x1 = cur[u2], x3 = cur[u2 + FN / 2];
            float s1, c1;
            __sincosf(step * (float)p, &s1, &c1);
            const float2 A0 = make_float2(x0.x + x2.x, x0.y + x2.y);
            const float dx = x0.x - x2.x, dy = x0.y - x2.y;
            const float2 A1 = make_float2(dx * c1 - dy * s1, dx * s1 + dy * c1);
            const float2 B0 = make_float2(x1.x + x3.x, x1.y + x3.y);
            const float ex = x1.x - x3.x, ey = x1.y - x3.y;
            const float tr = ex * c1 - ey * s1, ti = ex * s1 + ey * c1;
            const float2 B1 = make_float2(-ti, tr);          // i * ((x1-x3)*tw1)
            const float c3 = c1 * c1 - s1 * s1, s3 = 2.0f * c1 * s1;  // tw1^2
            const int O = (p << (s + 2)) | lo;
            const int q = 1 << s;
            nxt[O] = make_float2(A0.x + B0.x, A0.y + B0.y);
            const float fx = A0.x - B0.x, fy = A0.y - B0.y;
            nxt[O + 2 * q] = make_float2(fx * c3 - fy * s3, fx * s3 + fy * c3);
            nxt[O + q] = make_float2(A1.x + B1.x, A1.y + B1.y);
            const float gx = A1.x - B1.x, gy = A1.y - B1.y;
            nxt[O + 3 * q] = make_float2(gx * c3 - gy * s3, gx * s3 + gy * c3);
        }
        __syncthreads();
        float2* t = cur; cur = nxt; nxt = t;
    }

    // z[t]: out[2t] = Re z * inv, out[2t+1] = Im z * inv  (coalesced float2)
    const float inv = 1.0f / (float)Lk;
    float2* o2 = reinterpret_cast<float2*>(out + h * Lk);
#pragma unroll
    for (int t = tid; t < FN; t += 512) {
        const float2 z = cur[t];
        o2[t] = make_float2(z.x * inv, z.y * inv);
    }
}

extern "C" void kernel_launch(void* const* d_in, const int* in_sizes, int n_in,
                              void* d_out, int out_size) {
    // metadata order: w_ri, P_ri, B_ri, C_ri, log_dt, L (L fixed at 2048)
    k_fused<<<Hn, 512>>>(
        (const float*)d_in[0],
        (const float*)d_in[1],
        (const float*)d_in[2],
        (const float*)d_in[3],
        (const float*)d_in[4],
        (float*)d_out);
}